// round 2
// baseline (speedup 1.0000x reference)
#include <cuda_runtime.h>
#include <cstdint>

#define NJ 12
#define DM 128
#define NH 4
#define HD 32
#define TB 16
#define MROWS (TB*NJ)     // 192
#define THREADS 512

#define XS_STRIDE 132
#define QS_STRIDE 36
#define WB_STRIDE 132
#define WOS_STRIDE 36

// shared memory layout (floats)
#define OFF_XS   0
#define SZ_XS    (MROWS*XS_STRIDE)          // 25344
#define OFF_QB   (OFF_XS + SZ_XS)
#define SZ_QB    (MROWS*QS_STRIDE)          // 6912
#define OFF_KB   (OFF_QB + SZ_QB)
#define OFF_WB   (OFF_KB + SZ_QB)
#define SZ_WB    (96*WB_STRIDE)             // 12672
#define OFF_WOS  (OFF_WB + SZ_WB)
#define SZ_WOS   (DM*WOS_STRIDE)            // 4608
#define OFF_BQ   (OFF_WOS + SZ_WOS)
#define OFF_BK   (OFF_BQ + DM)
#define OFF_BV   (OFF_BK + DM)
#define OFF_BO   (OFF_BV + DM)
#define OFF_ADJ  (OFF_BO + DM)              // 144
#define OFF_KM   (OFF_ADJ + NJ*NJ)          // 192
#define SM_FLOATS (OFF_KM + MROWS)          // 57296 floats = 229184 B

__device__ __forceinline__ float tf32r(float f) {
    unsigned r;
    asm("cvt.rna.tf32.f32 %0, %1;" : "=r"(r) : "f"(f));
    return __uint_as_float(r);
}

// k-permutation: within each 8-group, logical r<4 -> 2r, r>=4 -> 2(r-4)+1.
// Makes mma fragment pairs (t, t+4) physically adjacent -> float2 LDS.
__device__ __forceinline__ int permc(int d) {
    int r = d & 7;
    return (d & ~7) + ((r < 4) ? (r << 1) : (((r - 4) << 1) | 1));
}

__device__ __forceinline__ void mma_tf32(float* d, const float* a, const float* b) {
    asm volatile(
        "mma.sync.aligned.m16n8k8.row.col.f32.tf32.tf32.f32 "
        "{%0,%1,%2,%3}, {%4,%5,%6,%7}, {%8,%9}, {%0,%1,%2,%3};"
        : "+f"(d[0]), "+f"(d[1]), "+f"(d[2]), "+f"(d[3])
        : "r"(__float_as_uint(a[0])), "r"(__float_as_uint(a[1])),
          "r"(__float_as_uint(a[2])), "r"(__float_as_uint(a[3])),
          "r"(__float_as_uint(b[0])), "r"(__float_as_uint(b[1])));
}

// store a float4 of logical cols [c, c+4) (c%4==0) at permuted positions, tf32-rounded
__device__ __forceinline__ void store_perm4(float* dst8base, int c, float4 v) {
    int base = (c & ~7) + ((c & 4) ? 1 : 0);
    dst8base[base]     = tf32r(v.x);
    dst8base[base + 2] = tf32r(v.y);
    dst8base[base + 4] = tf32r(v.z);
    dst8base[base + 6] = tf32r(v.w);
}

__global__ void __launch_bounds__(THREADS, 1)
cross_joint_attn_kernel(
    const float* __restrict__ x,    // (B, 12, 128)
    const float* __restrict__ vis,  // (B, 12)
    const float* __restrict__ Wq, const float* __restrict__ bq,
    const float* __restrict__ Wk, const float* __restrict__ bk,
    const float* __restrict__ Wv, const float* __restrict__ bv,
    const float* __restrict__ Wo, const float* __restrict__ bo,
    const float* __restrict__ bias_scale,
    const float* __restrict__ adj,
    float* __restrict__ out)
{
    extern __shared__ float sm[];
    float* Xs   = sm + OFF_XS;
    float* Qbuf = sm + OFF_QB;
    float* Kbuf = sm + OFF_KB;   // holds K, later overwritten by V
    float* Wbuf = sm + OFF_WB;   // Wq|Wk|Wv head slices (96 rows)
    float* Wos  = sm + OFF_WOS;  // Wo head slice (128 rows x 32)
    float* bqs  = sm + OFF_BQ;
    float* bks  = sm + OFF_BK;
    float* bvs  = sm + OFF_BV;
    float* bos  = sm + OFF_BO;
    float* adjb = sm + OFF_ADJ;
    float* kmsk = sm + OFF_KM;

    const int tid  = threadIdx.x;
    const int lane = tid & 31;
    const int warp = tid >> 5;
    const int cta  = blockIdx.x;
    const int batch0 = cta * TB;

    // ---- stage X (tf32, k-permuted) ----
    {
        const float4* xg = (const float4*)(x + (size_t)batch0 * NJ * DM);
        #pragma unroll
        for (int i = tid; i < MROWS * DM / 4; i += THREADS) {
            float4 v = xg[i];
            int idx = i * 4;
            int r = idx >> 7, c = idx & 127;
            store_perm4(Xs + r * XS_STRIDE, c, v);
        }
    }
    if (tid < DM) {
        bqs[tid] = bq[tid]; bks[tid] = bk[tid];
        bvs[tid] = bv[tid]; bos[tid] = bo[tid];
    }
    {
        float bsc = bias_scale[0];
        if (tid < NJ * NJ) adjb[tid] = adj[tid] * bsc;
        if (tid < MROWS)   kmsk[tid] = -10.0f * (1.0f - vis[(size_t)batch0 * NJ + tid]);
    }

    const int mg  = warp >> 2;      // 0..3 : 48 rows each
    const int ng  = warp & 3;       // 0..3
    const int gid = lane >> 2;      // 0..7
    const int tig = lane & 3;       // 0..3

    float y[3][4][4];               // persistent out-GEMM accumulators (48 regs)
    #pragma unroll
    for (int i = 0; i < 3; i++)
        #pragma unroll
        for (int j = 0; j < 4; j++)
            #pragma unroll
            for (int r = 0; r < 4; r++) y[i][j][r] = 0.0f;

    // attention thread mapping (threads 0..383)
    const int arow  = tid >> 1;          // 0..191 (valid if tid<384)
    const int ahalf = tid & 1;           // 16-col half
    const int alb   = arow / NJ;
    const int aln   = arow - alb * NJ;

    for (int h = 0; h < NH; ++h) {
        // ---- stage Wq|Wk|Wv head slices (96 x 128), tf32, k-permuted ----
        #pragma unroll
        for (int i = tid; i < 96 * DM / 4; i += THREADS) {
            int idx = i * 4;
            int row = idx >> 7, c = idx & 127;
            const float* wsrc = (row < 32) ? (Wq + ((size_t)(h * HD + row)) * DM)
                              : (row < 64) ? (Wk + ((size_t)(h * HD + row - 32)) * DM)
                                           : (Wv + ((size_t)(h * HD + row - 64)) * DM);
            float4 v = *(const float4*)(wsrc + c);
            store_perm4(Wbuf + row * WB_STRIDE, c, v);
        }
        __syncthreads();

        // ===== GEMM 1: [Q|K](192x64) = X @ [Wq_h|Wk_h]^T =====
        {
            float acc[3][2][4];
            #pragma unroll
            for (int i = 0; i < 3; i++)
                #pragma unroll
                for (int j = 0; j < 2; j++)
                    #pragma unroll
                    for (int r = 0; r < 4; r++) acc[i][j][r] = 0.0f;

            #pragma unroll
            for (int ks = 0; ks < 16; ks++) {
                int k0 = ks * 8;
                float a[3][4], bf[2][2];
                #pragma unroll
                for (int i = 0; i < 3; i++) {
                    int row = mg * 48 + i * 16 + gid;
                    float2 lo = *(const float2*)(Xs + row * XS_STRIDE + k0 + 2 * tig);
                    float2 hi = *(const float2*)(Xs + (row + 8) * XS_STRIDE + k0 + 2 * tig);
                    a[i][0] = lo.x; a[i][1] = hi.x; a[i][2] = lo.y; a[i][3] = hi.y;
                }
                #pragma unroll
                for (int j = 0; j < 2; j++) {
                    int n = ng * 16 + j * 8 + gid;
                    float2 b = *(const float2*)(Wbuf + n * WB_STRIDE + k0 + 2 * tig);
                    bf[j][0] = b.x; bf[j][1] = b.y;
                }
                #pragma unroll
                for (int i = 0; i < 3; i++)
                    #pragma unroll
                    for (int j = 0; j < 2; j++)
                        mma_tf32(acc[i][j], a[i], bf[j]);
            }
            #pragma unroll
            for (int i = 0; i < 3; i++) {
                int row = mg * 48 + i * 16 + gid;
                #pragma unroll
                for (int j = 0; j < 2; j++) {
                    int col = ng * 16 + j * 8 + 2 * tig;   // 0..63
                    float* C; float b0, b1; int d;
                    if (col < 32) { C = Qbuf; d = col;      b0 = bqs[h*HD+d]; b1 = bqs[h*HD+d+1]; }
                    else          { C = Kbuf; d = col - 32; b0 = bks[h*HD+d]; b1 = bks[h*HD+d+1]; }
                    int p0 = permc(d), p1 = permc(d + 1);
                    C[row * QS_STRIDE + p0]       = acc[i][j][0] + b0;
                    C[row * QS_STRIDE + p1]       = acc[i][j][1] + b1;
                    C[(row + 8) * QS_STRIDE + p0] = acc[i][j][2] + b0;
                    C[(row + 8) * QS_STRIDE + p1] = acc[i][j][3] + b1;
                }
            }
        }
        __syncthreads();

        // ===== scores (threads<384) + stage Wo (threads>=384) =====
        float s[NJ];
        if (tid < 384) {
            float q[16];
            const float4* qp = (const float4*)(Qbuf + arow * QS_STRIDE + ahalf * 16);
            #pragma unroll
            for (int j = 0; j < 4; j++) { float4 v = qp[j];
                q[4*j]=v.x; q[4*j+1]=v.y; q[4*j+2]=v.z; q[4*j+3]=v.w; }
            #pragma unroll
            for (int m = 0; m < NJ; m++) {
                const float4* kp = (const float4*)(Kbuf + (alb * NJ + m) * QS_STRIDE + ahalf * 16);
                float dot = 0.0f;
                #pragma unroll
                for (int j = 0; j < 4; j++) {
                    float4 v = kp[j];
                    dot += q[4*j]*v.x + q[4*j+1]*v.y + q[4*j+2]*v.z + q[4*j+3]*v.w;
                }
                dot += __shfl_xor_sync(0xFFFFFFFFu, dot, 1);
                s[m] = dot * 0.17677669529663687f + adjb[aln * NJ + m] + kmsk[alb * NJ + m];
            }
            float mx = s[0];
            #pragma unroll
            for (int m = 1; m < NJ; m++) mx = fmaxf(mx, s[m]);
            float sum = 0.0f;
            #pragma unroll
            for (int m = 0; m < NJ; m++) { s[m] = __expf(s[m] - mx); sum += s[m]; }
            float inv = 1.0f / sum;
            #pragma unroll
            for (int m = 0; m < NJ; m++) s[m] *= inv;
        } else {
            int e = tid - 384;   // 0..127 -> one Wo row each
            const float4* src = (const float4*)(Wo + (size_t)e * DM + h * HD);
            #pragma unroll
            for (int j = 0; j < 8; j++)
                store_perm4(Wos + e * WOS_STRIDE, j * 4, src[j]);
        }
        __syncthreads();

        // ===== GEMM 2: V(192x32) = X @ Wv_h^T  (into Kbuf) =====
        {
            float acc[3][4];
            #pragma unroll
            for (int i = 0; i < 3; i++)
                #pragma unroll
                for (int r = 0; r < 4; r++) acc[i][r] = 0.0f;
            #pragma unroll
            for (int ks = 0; ks < 16; ks++) {
                int k0 = ks * 8;
                float a[3][4], bf[2];
                #pragma unroll
                for (int i = 0; i < 3; i++) {
                    int row = mg * 48 + i * 16 + gid;
                    float2 lo = *(const float2*)(Xs + row * XS_STRIDE + k0 + 2 * tig);
                    float2 hi = *(const float2*)(Xs + (row + 8) * XS_STRIDE + k0 + 2 * tig);
                    a[i][0] = lo.x; a[i][1] = hi.x; a[i][2] = lo.y; a[i][3] = hi.y;
                }
                {
                    int n = 64 + ng * 8 + gid;
                    float2 b = *(const float2*)(Wbuf + n * WB_STRIDE + k0 + 2 * tig);
                    bf[0] = b.x; bf[1] = b.y;
                }
                #pragma unroll
                for (int i = 0; i < 3; i++) mma_tf32(acc[i], a[i], bf);
            }
            #pragma unroll
            for (int i = 0; i < 3; i++) {
                int row = mg * 48 + i * 16 + gid;
                int d = ng * 8 + 2 * tig;
                float b0 = bvs[h*HD+d], b1 = bvs[h*HD+d+1];
                int p0 = permc(d), p1 = permc(d + 1);
                Kbuf[row * QS_STRIDE + p0]       = acc[i][0] + b0;
                Kbuf[row * QS_STRIDE + p1]       = acc[i][1] + b1;
                Kbuf[(row + 8) * QS_STRIDE + p0] = acc[i][2] + b0;
                Kbuf[(row + 8) * QS_STRIDE + p1] = acc[i][3] + b1;
            }
        }
        __syncthreads();

        // ===== AO = P @ V  (threads<384), write tf32 into Qbuf =====
        if (tid < 384) {
            float ao[16];
            #pragma unroll
            for (int j = 0; j < 16; j++) ao[j] = 0.0f;
            #pragma unroll
            for (int m = 0; m < NJ; m++) {
                const float4* vp = (const float4*)(Kbuf + (alb * NJ + m) * QS_STRIDE + ahalf * 16);
                float p = s[m];
                #pragma unroll
                for (int j = 0; j < 4; j++) {
                    float4 v = vp[j];
                    ao[4*j]   += p * v.x; ao[4*j+1] += p * v.y;
                    ao[4*j+2] += p * v.z; ao[4*j+3] += p * v.w;
                }
            }
            float4* op = (float4*)(Qbuf + arow * QS_STRIDE + ahalf * 16);
            #pragma unroll
            for (int j = 0; j < 4; j++)
                op[j] = make_float4(tf32r(ao[4*j]), tf32r(ao[4*j+1]),
                                    tf32r(ao[4*j+2]), tf32r(ao[4*j+3]));
        }
        __syncthreads();

        // ===== GEMM 3: y += AO(192x32) @ Wo_h^T =====
        #pragma unroll
        for (int ks = 0; ks < 4; ks++) {
            int k0 = ks * 8;
            float a[3][4], bf[4][2];
            #pragma unroll
            for (int i = 0; i < 3; i++) {
                int row = mg * 48 + i * 16 + gid;
                float2 lo = *(const float2*)(Qbuf + row * QS_STRIDE + k0 + 2 * tig);
                float2 hi = *(const float2*)(Qbuf + (row + 8) * QS_STRIDE + k0 + 2 * tig);
                a[i][0] = lo.x; a[i][1] = hi.x; a[i][2] = lo.y; a[i][3] = hi.y;
            }
            #pragma unroll
            for (int j = 0; j < 4; j++) {
                int e = ng * 32 + j * 8 + gid;
                float2 b = *(const float2*)(Wos + e * WOS_STRIDE + k0 + 2 * tig);
                bf[j][0] = b.x; bf[j][1] = b.y;
            }
            #pragma unroll
            for (int i = 0; i < 3; i++)
                #pragma unroll
                for (int j = 0; j < 4; j++)
                    mma_tf32(y[i][j], a[i], bf[j]);
        }
        __syncthreads();
    }

    // ===== epilogue: y + bo -> global =====
    #pragma unroll
    for (int i = 0; i < 3; i++) {
        int row = mg * 48 + i * 16 + gid;
        #pragma unroll
        for (int j = 0; j < 4; j++) {
            int col = ng * 32 + j * 8 + 2 * tig;
            float b0 = bos[col], b1 = bos[col + 1];
            size_t base = ((size_t)cta * MROWS + row) * DM + col;
            *(float2*)(out + base)          = make_float2(y[i][j][0] + b0, y[i][j][1] + b1);
            *(float2*)(out + base + 8 * DM) = make_float2(y[i][j][2] + b0, y[i][j][3] + b1);
        }
    }
}

extern "C" void kernel_launch(void* const* d_in, const int* in_sizes, int n_in,
                              void* d_out, int out_size) {
    const float* x   = (const float*)d_in[0];
    const float* vis = (const float*)d_in[1];
    const float* Wq  = (const float*)d_in[2];
    const float* bq  = (const float*)d_in[3];
    const float* Wk  = (const float*)d_in[4];
    const float* bk  = (const float*)d_in[5];
    const float* Wv  = (const float*)d_in[6];
    const float* bv  = (const float*)d_in[7];
    const float* Wo  = (const float*)d_in[8];
    const float* bo  = (const float*)d_in[9];
    const float* bsc = (const float*)d_in[10];
    const float* adj = (const float*)d_in[11];
    float* out = (float*)d_out;

    const int B = in_sizes[0] / (NJ * DM);   // 16384
    const int grid = B / TB;                 // 1024
    const size_t smem = SM_FLOATS * sizeof(float);  // 229184 B

    static bool attr_set = false;
    if (!attr_set) {
        cudaFuncSetAttribute(cross_joint_attn_kernel,
                             cudaFuncAttributeMaxDynamicSharedMemorySize, (int)smem);
        attr_set = true;
    }
    cross_joint_attn_kernel<<<grid, THREADS, smem>>>(
        x, vis, Wq, bq, Wk, bk, Wv, bv, Wo, bo, bsc, adj, out);
}

// round 3
// speedup vs baseline: 1.0015x; 1.0015x over previous
#include <cuda_runtime.h>
#include <cstdint>

#define NJ 12
#define DM 128
#define NH 4
#define HD 32
#define TB 16
#define MROWS (TB*NJ)     // 192
#define THREADS 512

#define XS_STRIDE 132
#define QS_STRIDE 36
#define WB_STRIDE 132
#define WOS_STRIDE 36

// shared memory layout (floats)
#define OFF_XS   0
#define SZ_XS    (MROWS*XS_STRIDE)          // 25344
#define OFF_QB   (OFF_XS + SZ_XS)
#define SZ_QB    (MROWS*QS_STRIDE)          // 6912
#define OFF_KB   (OFF_QB + SZ_QB)
#define OFF_WB   (OFF_KB + SZ_QB)
#define SZ_WB    (96*WB_STRIDE)             // 12672
#define OFF_WOS  (OFF_WB + SZ_WB)
#define SZ_WOS   (DM*WOS_STRIDE)            // 4608
#define OFF_BQ   (OFF_WOS + SZ_WOS)
#define OFF_BK   (OFF_BQ + DM)
#define OFF_BV   (OFF_BK + DM)
#define OFF_BO   (OFF_BV + DM)
#define OFF_ADJ  (OFF_BO + DM)              // 144
#define OFF_KM   (OFF_ADJ + NJ*NJ)          // 192
#define SM_FLOATS (OFF_KM + MROWS)          // 57296 floats = 229184 B

__device__ __forceinline__ float tf32r(float f) {
    unsigned r;
    asm("cvt.rna.tf32.f32 %0, %1;" : "=r"(r) : "f"(f));
    return __uint_as_float(r);
}

// k-permutation: within each 8-group, logical r<4 -> 2r, r>=4 -> 2(r-4)+1.
// Makes mma fragment pairs (t, t+4) physically adjacent -> float2 LDS.
__device__ __forceinline__ int permc(int d) {
    int r = d & 7;
    return (d & ~7) + ((r < 4) ? (r << 1) : (((r - 4) << 1) | 1));
}

__device__ __forceinline__ void mma_tf32(float* d, const float* a, const float* b) {
    asm volatile(
        "mma.sync.aligned.m16n8k8.row.col.f32.tf32.tf32.f32 "
        "{%0,%1,%2,%3}, {%4,%5,%6,%7}, {%8,%9}, {%0,%1,%2,%3};"
        : "+f"(d[0]), "+f"(d[1]), "+f"(d[2]), "+f"(d[3])
        : "r"(__float_as_uint(a[0])), "r"(__float_as_uint(a[1])),
          "r"(__float_as_uint(a[2])), "r"(__float_as_uint(a[3])),
          "r"(__float_as_uint(b[0])), "r"(__float_as_uint(b[1])));
}

// store a float4 of logical cols [c, c+4) (c%4==0) at permuted positions, tf32-rounded
__device__ __forceinline__ void store_perm4(float* dst8base, int c, float4 v) {
    int base = (c & ~7) + ((c & 4) ? 1 : 0);
    dst8base[base]     = tf32r(v.x);
    dst8base[base + 2] = tf32r(v.y);
    dst8base[base + 4] = tf32r(v.z);
    dst8base[base + 6] = tf32r(v.w);
}

__global__ void __launch_bounds__(THREADS, 1)
cross_joint_attn_kernel(
    const float* __restrict__ x,    // (B, 12, 128)
    const float* __restrict__ vis,  // (B, 12)
    const float* __restrict__ Wq, const float* __restrict__ bq,
    const float* __restrict__ Wk, const float* __restrict__ bk,
    const float* __restrict__ Wv, const float* __restrict__ bv,
    const float* __restrict__ Wo, const float* __restrict__ bo,
    const float* __restrict__ bias_scale,
    const float* __restrict__ adj,
    float* __restrict__ out)
{
    extern __shared__ float sm[];
    float* Xs   = sm + OFF_XS;
    float* Qbuf = sm + OFF_QB;
    float* Kbuf = sm + OFF_KB;   // holds K, later overwritten by V
    float* Wbuf = sm + OFF_WB;   // Wq|Wk|Wv head slices (96 rows)
    float* Wos  = sm + OFF_WOS;  // Wo head slice (128 rows x 32)
    float* bqs  = sm + OFF_BQ;
    float* bks  = sm + OFF_BK;
    float* bvs  = sm + OFF_BV;
    float* bos  = sm + OFF_BO;
    float* adjb = sm + OFF_ADJ;
    float* kmsk = sm + OFF_KM;

    const int tid  = threadIdx.x;
    const int lane = tid & 31;
    const int warp = tid >> 5;
    const int cta  = blockIdx.x;
    const int batch0 = cta * TB;

    // ---- stage X (tf32, k-permuted) ----
    {
        const float4* xg = (const float4*)(x + (size_t)batch0 * NJ * DM);
        #pragma unroll
        for (int i = tid; i < MROWS * DM / 4; i += THREADS) {
            float4 v = xg[i];
            int idx = i * 4;
            int r = idx >> 7, c = idx & 127;
            store_perm4(Xs + r * XS_STRIDE, c, v);
        }
    }
    if (tid < DM) {
        bqs[tid] = bq[tid]; bks[tid] = bk[tid];
        bvs[tid] = bv[tid]; bos[tid] = bo[tid];
    }
    {
        float bsc = bias_scale[0];
        if (tid < NJ * NJ) adjb[tid] = adj[tid] * bsc;
        if (tid < MROWS)   kmsk[tid] = -10.0f * (1.0f - vis[(size_t)batch0 * NJ + tid]);
    }

    const int mg  = warp >> 2;      // 0..3 : 48 rows each
    const int ng  = warp & 3;       // 0..3
    const int gid = lane >> 2;      // 0..7
    const int tig = lane & 3;       // 0..3

    float y[3][4][4];               // persistent out-GEMM accumulators (48 regs)
    #pragma unroll
    for (int i = 0; i < 3; i++)
        #pragma unroll
        for (int j = 0; j < 4; j++)
            #pragma unroll
            for (int r = 0; r < 4; r++) y[i][j][r] = 0.0f;

    // attention thread mapping (threads 0..383)
    const int arow  = tid >> 1;          // 0..191 (valid if tid<384)
    const int ahalf = tid & 1;           // 16-col half
    const int alb   = arow / NJ;
    const int aln   = arow - alb * NJ;

    for (int h = 0; h < NH; ++h) {
        // ---- stage Wq|Wk|Wv head slices (96 x 128), tf32, k-permuted ----
        #pragma unroll
        for (int i = tid; i < 96 * DM / 4; i += THREADS) {
            int idx = i * 4;
            int row = idx >> 7, c = idx & 127;
            const float* wsrc = (row < 32) ? (Wq + ((size_t)(h * HD + row)) * DM)
                              : (row < 64) ? (Wk + ((size_t)(h * HD + row - 32)) * DM)
                                           : (Wv + ((size_t)(h * HD + row - 64)) * DM);
            float4 v = *(const float4*)(wsrc + c);
            store_perm4(Wbuf + row * WB_STRIDE, c, v);
        }
        __syncthreads();

        // ===== GEMM 1: [Q|K](192x64) = X @ [Wq_h|Wk_h]^T =====
        {
            float acc[3][2][4];
            #pragma unroll
            for (int i = 0; i < 3; i++)
                #pragma unroll
                for (int j = 0; j < 2; j++)
                    #pragma unroll
                    for (int r = 0; r < 4; r++) acc[i][j][r] = 0.0f;

            #pragma unroll
            for (int ks = 0; ks < 16; ks++) {
                int k0 = ks * 8;
                float a[3][4], bf[2][2];
                #pragma unroll
                for (int i = 0; i < 3; i++) {
                    int row = mg * 48 + i * 16 + gid;
                    float2 lo = *(const float2*)(Xs + row * XS_STRIDE + k0 + 2 * tig);
                    float2 hi = *(const float2*)(Xs + (row + 8) * XS_STRIDE + k0 + 2 * tig);
                    a[i][0] = lo.x; a[i][1] = hi.x; a[i][2] = lo.y; a[i][3] = hi.y;
                }
                #pragma unroll
                for (int j = 0; j < 2; j++) {
                    int n = ng * 16 + j * 8 + gid;
                    float2 b = *(const float2*)(Wbuf + n * WB_STRIDE + k0 + 2 * tig);
                    bf[j][0] = b.x; bf[j][1] = b.y;
                }
                #pragma unroll
                for (int i = 0; i < 3; i++)
                    #pragma unroll
                    for (int j = 0; j < 2; j++)
                        mma_tf32(acc[i][j], a[i], bf[j]);
            }
            #pragma unroll
            for (int i = 0; i < 3; i++) {
                int row = mg * 48 + i * 16 + gid;
                #pragma unroll
                for (int j = 0; j < 2; j++) {
                    int col = ng * 16 + j * 8 + 2 * tig;   // 0..63
                    float* C; float b0, b1; int d;
                    if (col < 32) { C = Qbuf; d = col;      b0 = bqs[h*HD+d]; b1 = bqs[h*HD+d+1]; }
                    else          { C = Kbuf; d = col - 32; b0 = bks[h*HD+d]; b1 = bks[h*HD+d+1]; }
                    int p0 = permc(d), p1 = permc(d + 1);
                    C[row * QS_STRIDE + p0]       = acc[i][j][0] + b0;
                    C[row * QS_STRIDE + p1]       = acc[i][j][1] + b1;
                    C[(row + 8) * QS_STRIDE + p0] = acc[i][j][2] + b0;
                    C[(row + 8) * QS_STRIDE + p1] = acc[i][j][3] + b1;
                }
            }
        }
        __syncthreads();

        // ===== scores (threads<384) + stage Wo (threads>=384) =====
        float s[NJ];
        if (tid < 384) {
            float q[16];
            const float4* qp = (const float4*)(Qbuf + arow * QS_STRIDE + ahalf * 16);
            #pragma unroll
            for (int j = 0; j < 4; j++) { float4 v = qp[j];
                q[4*j]=v.x; q[4*j+1]=v.y; q[4*j+2]=v.z; q[4*j+3]=v.w; }
            #pragma unroll
            for (int m = 0; m < NJ; m++) {
                const float4* kp = (const float4*)(Kbuf + (alb * NJ + m) * QS_STRIDE + ahalf * 16);
                float dot = 0.0f;
                #pragma unroll
                for (int j = 0; j < 4; j++) {
                    float4 v = kp[j];
                    dot += q[4*j]*v.x + q[4*j+1]*v.y + q[4*j+2]*v.z + q[4*j+3]*v.w;
                }
                dot += __shfl_xor_sync(0xFFFFFFFFu, dot, 1);
                s[m] = dot * 0.17677669529663687f + adjb[aln * NJ + m] + kmsk[alb * NJ + m];
            }
            float mx = s[0];
            #pragma unroll
            for (int m = 1; m < NJ; m++) mx = fmaxf(mx, s[m]);
            float sum = 0.0f;
            #pragma unroll
            for (int m = 0; m < NJ; m++) { s[m] = __expf(s[m] - mx); sum += s[m]; }
            float inv = 1.0f / sum;
            #pragma unroll
            for (int m = 0; m < NJ; m++) s[m] *= inv;
        } else {
            int e = tid - 384;   // 0..127 -> one Wo row each
            const float4* src = (const float4*)(Wo + (size_t)e * DM + h * HD);
            #pragma unroll
            for (int j = 0; j < 8; j++)
                store_perm4(Wos + e * WOS_STRIDE, j * 4, src[j]);
        }
        __syncthreads();

        // ===== GEMM 2: V(192x32) = X @ Wv_h^T  (into Kbuf) =====
        {
            float acc[3][4];
            #pragma unroll
            for (int i = 0; i < 3; i++)
                #pragma unroll
                for (int r = 0; r < 4; r++) acc[i][r] = 0.0f;
            #pragma unroll
            for (int ks = 0; ks < 16; ks++) {
                int k0 = ks * 8;
                float a[3][4], bf[2];
                #pragma unroll
                for (int i = 0; i < 3; i++) {
                    int row = mg * 48 + i * 16 + gid;
                    float2 lo = *(const float2*)(Xs + row * XS_STRIDE + k0 + 2 * tig);
                    float2 hi = *(const float2*)(Xs + (row + 8) * XS_STRIDE + k0 + 2 * tig);
                    a[i][0] = lo.x; a[i][1] = hi.x; a[i][2] = lo.y; a[i][3] = hi.y;
                }
                {
                    int n = 64 + ng * 8 + gid;
                    float2 b = *(const float2*)(Wbuf + n * WB_STRIDE + k0 + 2 * tig);
                    bf[0] = b.x; bf[1] = b.y;
                }
                #pragma unroll
                for (int i = 0; i < 3; i++) mma_tf32(acc[i], a[i], bf);
            }
            #pragma unroll
            for (int i = 0; i < 3; i++) {
                int row = mg * 48 + i * 16 + gid;
                int d = ng * 8 + 2 * tig;
                float b0 = bvs[h*HD+d], b1 = bvs[h*HD+d+1];
                int p0 = permc(d), p1 = permc(d + 1);
                Kbuf[row * QS_STRIDE + p0]       = acc[i][0] + b0;
                Kbuf[row * QS_STRIDE + p1]       = acc[i][1] + b1;
                Kbuf[(row + 8) * QS_STRIDE + p0] = acc[i][2] + b0;
                Kbuf[(row + 8) * QS_STRIDE + p1] = acc[i][3] + b1;
            }
        }
        __syncthreads();

        // ===== AO = P @ V  (threads<384), write tf32 into Qbuf =====
        if (tid < 384) {
            float ao[16];
            #pragma unroll
            for (int j = 0; j < 16; j++) ao[j] = 0.0f;
            #pragma unroll
            for (int m = 0; m < NJ; m++) {
                const float4* vp = (const float4*)(Kbuf + (alb * NJ + m) * QS_STRIDE + ahalf * 16);
                float p = s[m];
                #pragma unroll
                for (int j = 0; j < 4; j++) {
                    float4 v = vp[j];
                    ao[4*j]   += p * v.x; ao[4*j+1] += p * v.y;
                    ao[4*j+2] += p * v.z; ao[4*j+3] += p * v.w;
                }
            }
            float4* op = (float4*)(Qbuf + arow * QS_STRIDE + ahalf * 16);
            #pragma unroll
            for (int j = 0; j < 4; j++)
                op[j] = make_float4(tf32r(ao[4*j]), tf32r(ao[4*j+1]),
                                    tf32r(ao[4*j+2]), tf32r(ao[4*j+3]));
        }
        __syncthreads();

        // ===== GEMM 3: y += AO(192x32) @ Wo_h^T =====
        #pragma unroll
        for (int ks = 0; ks < 4; ks++) {
            int k0 = ks * 8;
            float a[3][4], bf[4][2];
            #pragma unroll
            for (int i = 0; i < 3; i++) {
                int row = mg * 48 + i * 16 + gid;
                float2 lo = *(const float2*)(Qbuf + row * QS_STRIDE + k0 + 2 * tig);
                float2 hi = *(const float2*)(Qbuf + (row + 8) * QS_STRIDE + k0 + 2 * tig);
                a[i][0] = lo.x; a[i][1] = hi.x; a[i][2] = lo.y; a[i][3] = hi.y;
            }
            #pragma unroll
            for (int j = 0; j < 4; j++) {
                int e = ng * 32 + j * 8 + gid;
                float2 b = *(const float2*)(Wos + e * WOS_STRIDE + k0 + 2 * tig);
                bf[j][0] = b.x; bf[j][1] = b.y;
            }
            #pragma unroll
            for (int i = 0; i < 3; i++)
                #pragma unroll
                for (int j = 0; j < 4; j++)
                    mma_tf32(y[i][j], a[i], bf[j]);
        }
        __syncthreads();
    }

    // ===== epilogue: y + bo -> global =====
    #pragma unroll
    for (int i = 0; i < 3; i++) {
        int row = mg * 48 + i * 16 + gid;
        #pragma unroll
        for (int j = 0; j < 4; j++) {
            int col = ng * 32 + j * 8 + 2 * tig;
            float b0 = bos[col], b1 = bos[col + 1];
            size_t base = ((size_t)cta * MROWS + row) * DM + col;
            *(float2*)(out + base)          = make_float2(y[i][j][0] + b0, y[i][j][1] + b1);
            *(float2*)(out + base + 8 * DM) = make_float2(y[i][j][2] + b0, y[i][j][3] + b1);
        }
    }
}

extern "C" void kernel_launch(void* const* d_in, const int* in_sizes, int n_in,
                              void* d_out, int out_size) {
    const float* x   = (const float*)d_in[0];
    const float* vis = (const float*)d_in[1];
    const float* Wq  = (const float*)d_in[2];
    const float* bq  = (const float*)d_in[3];
    const float* Wk  = (const float*)d_in[4];
    const float* bk  = (const float*)d_in[5];
    const float* Wv  = (const float*)d_in[6];
    const float* bv  = (const float*)d_in[7];
    const float* Wo  = (const float*)d_in[8];
    const float* bo  = (const float*)d_in[9];
    const float* bsc = (const float*)d_in[10];
    const float* adj = (const float*)d_in[11];
    float* out = (float*)d_out;

    const int B = in_sizes[0] / (NJ * DM);   // 16384
    const int grid = B / TB;                 // 1024
    const size_t smem = SM_FLOATS * sizeof(float);  // 229184 B

    static bool attr_set = false;
    if (!attr_set) {
        cudaFuncSetAttribute(cross_joint_attn_kernel,
                             cudaFuncAttributeMaxDynamicSharedMemorySize, (int)smem);
        attr_set = true;
    }
    cross_joint_attn_kernel<<<grid, THREADS, smem>>>(
        x, vis, Wq, bq, Wk, bk, Wv, bv, Wo, bo, bsc, adj, out);
}

// round 5
// speedup vs baseline: 1.1774x; 1.1756x over previous
#include <cuda_runtime.h>
#include <cstdint>

#define THREADS 256
#define TB 8
#define NJ 12
#define DM 128
#define NH 4
#define HD 32
#define MR 96             // rows per CTA = TB*NJ

// ---- shared memory layout (float offsets) ----
#define T_STRIDE 132       // tf32 tile stride (X, W, AO, Wo)
#define QKV_STRIDE 100     // scalar QKV buffer stride

#define OFF_X    0                      // 96 x 132
#define OFF_W    (OFF_X + MR*T_STRIDE)  // 12672 : Wqkv stage 96 x 132
#define OFF_WO   OFF_X                  // final Wo stage 128 x 132 (reuses X+W)
#define OFF_AO   (OFF_W + MR*T_STRIDE)  // 25344 : AO_all 96 x 132
#define OFF_QKV  (OFF_AO + MR*T_STRIDE) // 38016 : 96 x 100
#define OFF_BQ   (OFF_QKV + MR*QKV_STRIDE) // 47616
#define OFF_BK   (OFF_BQ + DM)
#define OFF_BV   (OFF_BK + DM)
#define OFF_BO   (OFF_BV + DM)
#define OFF_ADJ  (OFF_BO + DM)          // 144
#define OFF_KM   (OFF_ADJ + NJ*NJ)      // 96
#define SM_FLOATS (OFF_KM + MR)         // 48368 floats = 193472 B

__device__ __forceinline__ float tf32r(float f) {
    unsigned r; asm("cvt.rna.tf32.f32 %0, %1;" : "=r"(r) : "f"(f));
    return __uint_as_float(r);
}

// k-permutation within 8-groups: fragment pairs (t, t+4) physically adjacent -> float2 LDS
__device__ __forceinline__ void store_perm4(float* dst_row, int c, float4 v) {
    int base = (c & ~7) + ((c & 4) ? 1 : 0);
    dst_row[base]     = tf32r(v.x);
    dst_row[base + 2] = tf32r(v.y);
    dst_row[base + 4] = tf32r(v.z);
    dst_row[base + 6] = tf32r(v.w);
}

__device__ __forceinline__ void mma_tf32(float* d, const float* a, const float* b) {
    asm volatile(
        "mma.sync.aligned.m16n8k8.row.col.f32.tf32.tf32.f32 "
        "{%0,%1,%2,%3}, {%4,%5,%6,%7}, {%8,%9}, {%0,%1,%2,%3};"
        : "+f"(d[0]), "+f"(d[1]), "+f"(d[2]), "+f"(d[3])
        : "r"(__float_as_uint(a[0])), "r"(__float_as_uint(a[1])),
          "r"(__float_as_uint(a[2])), "r"(__float_as_uint(a[3])),
          "r"(__float_as_uint(b[0])), "r"(__float_as_uint(b[1])));
}

__global__ void __launch_bounds__(THREADS, 1)
cross_joint_attn_kernel(
    const float* __restrict__ x, const float* __restrict__ vis,
    const float* __restrict__ Wq, const float* __restrict__ bq,
    const float* __restrict__ Wk, const float* __restrict__ bk,
    const float* __restrict__ Wv, const float* __restrict__ bv,
    const float* __restrict__ Wo, const float* __restrict__ bo,
    const float* __restrict__ bias_scale, const float* __restrict__ adj,
    float* __restrict__ out)
{
    extern __shared__ float sm[];
    float* Xs   = sm + OFF_X;
    float* Ws   = sm + OFF_W;
    float* WOs  = sm + OFF_WO;
    float* AOs  = sm + OFF_AO;
    float* QKV  = sm + OFF_QKV;
    float* bqs  = sm + OFF_BQ;
    float* bks  = sm + OFF_BK;
    float* bvs  = sm + OFF_BV;
    float* bos  = sm + OFF_BO;
    float* adjb = sm + OFF_ADJ;
    float* kmsk = sm + OFF_KM;

    const int tid  = threadIdx.x;
    const int lane = tid & 31;
    const int warp = tid >> 5;
    const int cta  = blockIdx.x;

    const int mg  = warp >> 2;       // 0..1 : 48-row group
    const int ng  = warp & 3;        // 0..3
    const int gid = lane >> 2;       // 0..7
    const int tig = lane & 3;        // 0..3

    // ---- stage X (96x128, tf32, permuted) ----
    {
        const float4* xg = (const float4*)(x + (size_t)cta * MR * DM);
        #pragma unroll
        for (int j = 0; j < 12; j++) {
            int i = tid + j * THREADS;            // < 3072
            float4 v = xg[i];
            int row = i >> 5, kk = (i & 31) * 4;
            store_perm4(Xs + row * T_STRIDE, kk, v);
        }
    }
    if (tid < DM) {
        bqs[tid] = bq[tid]; bks[tid] = bk[tid];
        bvs[tid] = bv[tid]; bos[tid] = bo[tid];
    }
    if (tid < NJ * NJ) adjb[tid] = adj[tid] * bias_scale[0];
    if (tid < MR)      kmsk[tid] = -10.0f * (1.0f - vis[(size_t)cta * MR + tid]);

    for (int h = 0; h < NH; ++h) {
        // ---- stage [Wq|Wk|Wv]_h (96x128, tf32, permuted) ----
        #pragma unroll
        for (int j = 0; j < 12; j++) {
            int i = tid + j * THREADS;
            int row = i >> 5, kk = (i & 31) * 4;
            const float* src = (row < 32) ? (Wq + (size_t)(h * HD + row) * DM)
                             : (row < 64) ? (Wk + (size_t)(h * HD + row - 32) * DM)
                                          : (Wv + (size_t)(h * HD + row - 64) * DM);
            float4 v = *(const float4*)(src + kk);
            store_perm4(Ws + row * T_STRIDE, kk, v);
        }
        __syncthreads();

        // ===== GEMM1: [Q|K|V](96x96) = X @ Wqkv^T =====
        float acc[3][3][4];
        #pragma unroll
        for (int i = 0; i < 3; i++)
            #pragma unroll
            for (int j = 0; j < 3; j++)
                #pragma unroll
                for (int r = 0; r < 4; r++) acc[i][j][r] = 0.0f;

        #pragma unroll
        for (int ks = 0; ks < 16; ks++) {
            int k0 = ks * 8;
            float a[3][4], bf[3][2];
            #pragma unroll
            for (int i = 0; i < 3; i++) {
                int row = mg * 48 + i * 16 + gid;
                float2 lo = *(const float2*)(Xs + row * T_STRIDE + k0 + 2 * tig);
                float2 hi = *(const float2*)(Xs + (row + 8) * T_STRIDE + k0 + 2 * tig);
                a[i][0] = lo.x; a[i][1] = hi.x; a[i][2] = lo.y; a[i][3] = hi.y;
            }
            #pragma unroll
            for (int j = 0; j < 3; j++) {
                int n = ng * 24 + j * 8 + gid;
                float2 b = *(const float2*)(Ws + n * T_STRIDE + k0 + 2 * tig);
                bf[j][0] = b.x; bf[j][1] = b.y;
            }
            #pragma unroll
            for (int i = 0; i < 3; i++)
                #pragma unroll
                for (int j = 0; j < 3; j++)
                    mma_tf32(acc[i][j], a[i], bf[j]);
        }
        // bias + scatter to scalar QKV buffer
        #pragma unroll
        for (int i = 0; i < 3; i++) {
            int row = mg * 48 + i * 16 + gid;
            #pragma unroll
            for (int j = 0; j < 3; j++) {
                int col = ng * 24 + j * 8 + 2 * tig;
                float b0, b1;
                if (col < 32)      { b0 = bqs[h*HD+col];      b1 = bqs[h*HD+col+1]; }
                else if (col < 64) { b0 = bks[h*HD+col-32];   b1 = bks[h*HD+col-31]; }
                else               { b0 = bvs[h*HD+col-64];   b1 = bvs[h*HD+col-63]; }
                QKV[row * QKV_STRIDE + col]           = acc[i][j][0] + b0;
                QKV[row * QKV_STRIDE + col + 1]       = acc[i][j][1] + b1;
                QKV[(row + 8) * QKV_STRIDE + col]     = acc[i][j][2] + b0;
                QKV[(row + 8) * QKV_STRIDE + col + 1] = acc[i][j][3] + b1;
            }
        }
        __syncthreads();

        // ===== attention: 2 threads per row (tid<192) =====
        if (tid < 192) {
            int row  = tid >> 1;
            int half = tid & 1;
            int lb = row / NJ, ln = row - lb * NJ;

            float q[16];
            const float4* qp = (const float4*)(QKV + row * QKV_STRIDE + half * 16);
            #pragma unroll
            for (int j = 0; j < 4; j++) { float4 v = qp[j];
                q[4*j]=v.x; q[4*j+1]=v.y; q[4*j+2]=v.z; q[4*j+3]=v.w; }

            float s[NJ];
            #pragma unroll
            for (int m = 0; m < NJ; m++) {
                const float4* kp = (const float4*)(QKV + (lb * NJ + m) * QKV_STRIDE + 32 + half * 16);
                float dot = 0.0f;
                #pragma unroll
                for (int j = 0; j < 4; j++) {
                    float4 v = kp[j];
                    dot += q[4*j]*v.x + q[4*j+1]*v.y + q[4*j+2]*v.z + q[4*j+3]*v.w;
                }
                dot += __shfl_xor_sync(0xFFFFFFFFu, dot, 1);
                s[m] = dot * 0.17677669529663687f + adjb[ln * NJ + m] + kmsk[lb * NJ + m];
            }
            float mx = s[0];
            #pragma unroll
            for (int m = 1; m < NJ; m++) mx = fmaxf(mx, s[m]);
            float sum = 0.0f;
            #pragma unroll
            for (int m = 0; m < NJ; m++) { s[m] = __expf(s[m] - mx); sum += s[m]; }
            float inv = 1.0f / sum;

            float ao[16];
            #pragma unroll
            for (int j = 0; j < 16; j++) ao[j] = 0.0f;
            #pragma unroll
            for (int m = 0; m < NJ; m++) {
                float p = s[m] * inv;
                const float4* vp = (const float4*)(QKV + (lb * NJ + m) * QKV_STRIDE + 64 + half * 16);
                #pragma unroll
                for (int j = 0; j < 4; j++) {
                    float4 v = vp[j];
                    ao[4*j]   += p * v.x; ao[4*j+1] += p * v.y;
                    ao[4*j+2] += p * v.z; ao[4*j+3] += p * v.w;
                }
            }
            // write AO (tf32, permuted) at k-offset h*32 + half*16
            int c0 = h * HD + half * 16;
            float* dst = AOs + row * T_STRIDE;
            #pragma unroll
            for (int j = 0; j < 4; j++)
                store_perm4(dst, c0 + 4 * j,
                    make_float4(ao[4*j], ao[4*j+1], ao[4*j+2], ao[4*j+3]));
        }
        __syncthreads();
    }

    // ---- stage Wo (128x128, tf32, permuted) into freed X|W region ----
    #pragma unroll
    for (int j = 0; j < 16; j++) {
        int i = tid + j * THREADS;               // < 4096
        int row = i >> 5, kk = (i & 31) * 4;
        float4 v = *(const float4*)(Wo + (size_t)row * DM + kk);
        store_perm4(WOs + row * T_STRIDE, kk, v);
    }
    __syncthreads();

    // ===== final GEMM: Y(96x128) = AO_all @ Wo^T, k=128 =====
    float y[3][4][4];
    #pragma unroll
    for (int i = 0; i < 3; i++)
        #pragma unroll
        for (int j = 0; j < 4; j++)
            #pragma unroll
            for (int r = 0; r < 4; r++) y[i][j][r] = 0.0f;

    #pragma unroll
    for (int ks = 0; ks < 16; ks++) {
        int k0 = ks * 8;
        float a[3][4], bf[4][2];
        #pragma unroll
        for (int i = 0; i < 3; i++) {
            int row = mg * 48 + i * 16 + gid;
            float2 lo = *(const float2*)(AOs + row * T_STRIDE + k0 + 2 * tig);
            float2 hi = *(const float2*)(AOs + (row + 8) * T_STRIDE + k0 + 2 * tig);
            a[i][0] = lo.x; a[i][1] = hi.x; a[i][2] = lo.y; a[i][3] = hi.y;
        }
        #pragma unroll
        for (int j = 0; j < 4; j++) {
            int e = ng * 32 + j * 8 + gid;
            float2 b = *(const float2*)(WOs + e * T_STRIDE + k0 + 2 * tig);
            bf[j][0] = b.x; bf[j][1] = b.y;
        }
        #pragma unroll
        for (int i = 0; i < 3; i++)
            #pragma unroll
            for (int j = 0; j < 4; j++)
                mma_tf32(y[i][j], a[i], bf[j]);
    }

    // ===== epilogue: y + bo -> global =====
    #pragma unroll
    for (int i = 0; i < 3; i++) {
        int row = mg * 48 + i * 16 + gid;
        #pragma unroll
        for (int j = 0; j < 4; j++) {
            int col = ng * 32 + j * 8 + 2 * tig;
            float b0 = bos[col], b1 = bos[col + 1];
            size_t base = ((size_t)cta * MR + row) * DM + col;
            *(float2*)(out + base)          = make_float2(y[i][j][0] + b0, y[i][j][1] + b1);
            *(float2*)(out + base + 8 * DM) = make_float2(y[i][j][2] + b0, y[i][j][3] + b1);
        }
    }
}

extern "C" void kernel_launch(void* const* d_in, const int* in_sizes, int n_in,
                              void* d_out, int out_size) {
    const float* x   = (const float*)d_in[0];
    const float* vis = (const float*)d_in[1];
    const float* Wq  = (const float*)d_in[2];
    const float* bq  = (const float*)d_in[3];
    const float* Wk  = (const float*)d_in[4];
    const float* bk  = (const float*)d_in[5];
    const float* Wv  = (const float*)d_in[6];
    const float* bv  = (const float*)d_in[7];
    const float* Wo  = (const float*)d_in[8];
    const float* bo  = (const float*)d_in[9];
    const float* bsc = (const float*)d_in[10];
    const float* adj = (const float*)d_in[11];
    float* out = (float*)d_out;

    const int B = in_sizes[0] / (NJ * DM);     // 16384
    const int grid = B / TB;                   // 2048
    const size_t smem = SM_FLOATS * sizeof(float);   // 193472 B

    static bool attr_set = false;
    if (!attr_set) {
        cudaFuncSetAttribute(cross_joint_attn_kernel,
                             cudaFuncAttributeMaxDynamicSharedMemorySize, (int)smem);
        attr_set = true;
    }
    cross_joint_attn_kernel<<<grid, THREADS, smem>>>(
        x, vis, Wq, bq, Wk, bk, Wv, bv, Wo, bo, bsc, adj, out);
}

// round 6
// speedup vs baseline: 1.5425x; 1.3101x over previous
#include <cuda_runtime.h>
#include <cstdint>

#define THREADS 256
#define TB 8
#define NJ 12
#define DM 128
#define NH 4
#define HD 32
#define MR 96              // rows per CTA

#define TSTR 132           // tile stride (floats) for X/W/AO/Wo
#define QSTR 100           // scalar QKV buffer stride

// float offsets
#define OFF_X    0                        // 96 x 132
#define OFF_W    (OFF_X + MR*TSTR)        // 12672
#define OFF_AO   (OFF_W + MR*TSTR)        // 25344
#define OFF_QKV  (OFF_AO + MR*TSTR)       // 38016 : 96 x 100
#define OFF_BQ   (OFF_QKV + MR*QSTR)      // 47616
#define OFF_BK   (OFF_BQ + DM)
#define OFF_BV   (OFF_BK + DM)
#define OFF_BO   (OFF_BV + DM)
#define OFF_ADJ  (OFF_BO + DM)
#define OFF_KM   (OFF_ADJ + NJ*NJ)
#define SM_FLOATS (OFF_KM + MR)           // 48368 floats = 193472 B
#define OFF_WO   OFF_X                    // final Wo 128x132 reuses X|W region

__device__ __forceinline__ float tf32r(float f) {
    unsigned r; asm("cvt.rna.tf32.f32 %0, %1;" : "=r"(r) : "f"(f));
    return __uint_as_float(r);
}
__device__ __forceinline__ float4 tf32r4(float4 v) {
    return make_float4(tf32r(v.x), tf32r(v.y), tf32r(v.z), tf32r(v.w));
}

__device__ __forceinline__ void ldsm_x4(uint32_t* r, uint32_t addr) {
    asm volatile("ldmatrix.sync.aligned.m8n8.x4.shared.b16 {%0,%1,%2,%3}, [%4];"
        : "=r"(r[0]), "=r"(r[1]), "=r"(r[2]), "=r"(r[3]) : "r"(addr));
}
__device__ __forceinline__ void ldsm_x2(uint32_t* r, uint32_t addr) {
    asm volatile("ldmatrix.sync.aligned.m8n8.x2.shared.b16 {%0,%1}, [%2];"
        : "=r"(r[0]), "=r"(r[1]) : "r"(addr));
}
__device__ __forceinline__ void mma8(float* d, const uint32_t* a, const uint32_t* b) {
    asm volatile(
        "mma.sync.aligned.m16n8k8.row.col.f32.tf32.tf32.f32 "
        "{%0,%1,%2,%3}, {%4,%5,%6,%7}, {%8,%9}, {%0,%1,%2,%3};"
        : "+f"(d[0]), "+f"(d[1]), "+f"(d[2]), "+f"(d[3])
        : "r"(a[0]), "r"(a[1]), "r"(a[2]), "r"(a[3]), "r"(b[0]), "r"(b[1]));
}

__global__ void __launch_bounds__(THREADS, 1)
cross_joint_attn_kernel(
    const float* __restrict__ x, const float* __restrict__ vis,
    const float* __restrict__ Wq, const float* __restrict__ bq,
    const float* __restrict__ Wk, const float* __restrict__ bk,
    const float* __restrict__ Wv, const float* __restrict__ bv,
    const float* __restrict__ Wo, const float* __restrict__ bo,
    const float* __restrict__ bias_scale, const float* __restrict__ adj,
    float* __restrict__ out)
{
    extern __shared__ __align__(16) float sm[];
    float* Xs   = sm + OFF_X;
    float* Ws   = sm + OFF_W;
    float* AOs  = sm + OFF_AO;
    float* WOs  = sm + OFF_WO;
    float* QKV  = sm + OFF_QKV;
    float* bqs  = sm + OFF_BQ;
    float* bks  = sm + OFF_BK;
    float* bvs  = sm + OFF_BV;
    float* bos  = sm + OFF_BO;
    float* adjb = sm + OFF_ADJ;
    float* kmsk = sm + OFF_KM;

    const int tid  = threadIdx.x;
    const int lane = tid & 31;
    const int warp = tid >> 5;
    const int cta  = blockIdx.x;
    const int gid  = lane >> 2;
    const int tig  = lane & 3;

    const uint32_t sb   = (uint32_t)__cvta_generic_to_shared(sm);
    const uint32_t sbX  = sb + OFF_X * 4;
    const uint32_t sbW  = sb + OFF_W * 4;
    const uint32_t sbAO = sb + OFF_AO * 4;
    const uint32_t sbWO = sb + OFF_WO * 4;

    // ---- stage X (96x128 tf32 natural) ----
    {
        const float4* xg = (const float4*)(x + (size_t)cta * MR * DM);
        #pragma unroll
        for (int j = 0; j < 12; j++) {
            int i = tid + j * THREADS;           // < 3072
            int row = i >> 5, kk = (i & 31) * 4;
            *(float4*)(Xs + row * TSTR + kk) = tf32r4(xg[i]);
        }
    }
    // ---- stage W head 0 ----
    #pragma unroll
    for (int j = 0; j < 12; j++) {
        int i = tid + j * THREADS;
        int row = i >> 5, kk = (i & 31) * 4;
        const float* src = (row < 32) ? (Wq + (size_t)row * DM)
                         : (row < 64) ? (Wk + (size_t)(row - 32) * DM)
                                      : (Wv + (size_t)(row - 64) * DM);
        *(float4*)(Ws + row * TSTR + kk) = tf32r4(*(const float4*)(src + kk));
    }
    if (tid < DM) {
        bqs[tid] = bq[tid]; bks[tid] = bk[tid];
        bvs[tid] = bv[tid]; bos[tid] = bo[tid];
    }
    if (tid < NJ * NJ) adjb[tid] = adj[tid] * bias_scale[0];
    if (tid < MR)      kmsk[tid] = -10.0f * (1.0f - vis[(size_t)cta * MR + tid]);
    __syncthreads();

    for (int h = 0; h < NH; ++h) {
        // ===== GEMM1 (warps 0..5, mg2 x ng3): QKV(96x96) = X @ Wqkv^T =====
        if (warp < 6) {
            const int mg = warp / 3, ng = warp - mg * 3;
            uint32_t aaddr[3], baddr[4];
            #pragma unroll
            for (int i = 0; i < 3; i++)
                aaddr[i] = sbX + (uint32_t)((mg * 48 + i * 16 + (lane & 15)) * TSTR) * 4
                               + ((lane >> 4) * 16);
            #pragma unroll
            for (int j = 0; j < 4; j++)
                baddr[j] = sbW + (uint32_t)((ng * 32 + j * 8 + (lane & 7)) * TSTR) * 4
                               + (((lane >> 3) & 1) * 16);

            float acc[3][4][4];
            #pragma unroll
            for (int i = 0; i < 3; i++)
                #pragma unroll
                for (int j = 0; j < 4; j++)
                    #pragma unroll
                    for (int r = 0; r < 4; r++) acc[i][j][r] = 0.0f;

            #pragma unroll
            for (int ks = 0; ks < 16; ks++) {
                uint32_t a[3][4], b[4][2];
                #pragma unroll
                for (int i = 0; i < 3; i++) ldsm_x4(a[i], aaddr[i] + ks * 32);
                #pragma unroll
                for (int j = 0; j < 4; j++) ldsm_x2(b[j], baddr[j] + ks * 32);
                #pragma unroll
                for (int i = 0; i < 3; i++)
                    #pragma unroll
                    for (int j = 0; j < 4; j++) mma8(acc[i][j], a[i], b[j]);
            }
            // bias + scatter (float2)
            #pragma unroll
            for (int i = 0; i < 3; i++) {
                int row = mg * 48 + i * 16 + gid;
                #pragma unroll
                for (int j = 0; j < 4; j++) {
                    int col = ng * 32 + j * 8 + 2 * tig;
                    float b0, b1;
                    if (col < 32)      { b0 = bqs[h*HD+col];    b1 = bqs[h*HD+col+1]; }
                    else if (col < 64) { b0 = bks[h*HD+col-32]; b1 = bks[h*HD+col-31]; }
                    else               { b0 = bvs[h*HD+col-64]; b1 = bvs[h*HD+col-63]; }
                    *(float2*)(QKV + row * QSTR + col) =
                        make_float2(acc[i][j][0] + b0, acc[i][j][1] + b1);
                    *(float2*)(QKV + (row + 8) * QSTR + col) =
                        make_float2(acc[i][j][2] + b0, acc[i][j][3] + b1);
                }
            }
        }
        __syncthreads();

        // ===== attention (tid<192) || stage W_{h+1} (tid>=192) =====
        if (tid < 192) {
            int row  = tid >> 1;
            int half = tid & 1;
            int lb = row / NJ, ln = row - lb * NJ;

            float q[16];
            const float4* qp = (const float4*)(QKV + row * QSTR + half * 16);
            #pragma unroll
            for (int j = 0; j < 4; j++) { float4 v = qp[j];
                q[4*j]=v.x; q[4*j+1]=v.y; q[4*j+2]=v.z; q[4*j+3]=v.w; }

            float s[NJ];
            #pragma unroll
            for (int m = 0; m < NJ; m++) {
                const float4* kp = (const float4*)(QKV + (lb * NJ + m) * QSTR + 32 + half * 16);
                float dot = 0.0f;
                #pragma unroll
                for (int j = 0; j < 4; j++) {
                    float4 v = kp[j];
                    dot += q[4*j]*v.x + q[4*j+1]*v.y + q[4*j+2]*v.z + q[4*j+3]*v.w;
                }
                dot += __shfl_xor_sync(0xFFFFFFFFu, dot, 1);
                s[m] = dot * 0.17677669529663687f + adjb[ln * NJ + m] + kmsk[lb * NJ + m];
            }
            float mx = s[0];
            #pragma unroll
            for (int m = 1; m < NJ; m++) mx = fmaxf(mx, s[m]);
            float sum = 0.0f;
            #pragma unroll
            for (int m = 0; m < NJ; m++) { s[m] = __expf(s[m] - mx); sum += s[m]; }
            float inv = 1.0f / sum;

            float ao[16];
            #pragma unroll
            for (int j = 0; j < 16; j++) ao[j] = 0.0f;
            #pragma unroll
            for (int m = 0; m < NJ; m++) {
                float p = s[m] * inv;
                const float4* vp = (const float4*)(QKV + (lb * NJ + m) * QSTR + 64 + half * 16);
                #pragma unroll
                for (int j = 0; j < 4; j++) {
                    float4 v = vp[j];
                    ao[4*j]   += p * v.x; ao[4*j+1] += p * v.y;
                    ao[4*j+2] += p * v.z; ao[4*j+3] += p * v.w;
                }
            }
            float* dst = AOs + row * TSTR + h * HD + half * 16;
            #pragma unroll
            for (int j = 0; j < 4; j++)
                *(float4*)(dst + 4 * j) = make_float4(
                    tf32r(ao[4*j]), tf32r(ao[4*j+1]), tf32r(ao[4*j+2]), tf32r(ao[4*j+3]));
        } else if (h < 3) {
            // warps 6,7: stage next head's Wqkv (W buffer is idle during attention)
            int t2 = tid - 192;
            #pragma unroll
            for (int j = 0; j < 48; j++) {
                int i = t2 + j * 64;                 // < 3072
                int row = i >> 5, kk = (i & 31) * 4;
                const float* src = (row < 32) ? (Wq + (size_t)((h+1) * HD + row) * DM)
                                 : (row < 64) ? (Wk + (size_t)((h+1) * HD + row - 32) * DM)
                                              : (Wv + (size_t)((h+1) * HD + row - 64) * DM);
                *(float4*)(Ws + row * TSTR + kk) = tf32r4(*(const float4*)(src + kk));
            }
        }
        __syncthreads();
    }

    // ---- stage Wo (128x128 tf32 natural) into freed X|W region ----
    #pragma unroll
    for (int j = 0; j < 16; j++) {
        int i = tid + j * THREADS;                   // < 4096
        int row = i >> 5, kk = (i & 31) * 4;
        *(float4*)(WOs + row * TSTR + kk) = tf32r4(*(const float4*)(Wo + (size_t)row * DM + kk));
    }
    __syncthreads();

    // ===== final GEMM (8 warps, mg2 x ng4): Y(96x128) = AO @ Wo^T =====
    {
        const int fmg = warp >> 2, fng = warp & 3;
        uint32_t aaddr[3], baddr[4];
        #pragma unroll
        for (int i = 0; i < 3; i++)
            aaddr[i] = sbAO + (uint32_t)((fmg * 48 + i * 16 + (lane & 15)) * TSTR) * 4
                            + ((lane >> 4) * 16);
        #pragma unroll
        for (int j = 0; j < 4; j++)
            baddr[j] = sbWO + (uint32_t)((fng * 32 + j * 8 + (lane & 7)) * TSTR) * 4
                            + (((lane >> 3) & 1) * 16);

        float y[3][4][4];
        #pragma unroll
        for (int i = 0; i < 3; i++)
            #pragma unroll
            for (int j = 0; j < 4; j++)
                #pragma unroll
                for (int r = 0; r < 4; r++) y[i][j][r] = 0.0f;

        #pragma unroll
        for (int ks = 0; ks < 16; ks++) {
            uint32_t a[3][4], b[4][2];
            #pragma unroll
            for (int i = 0; i < 3; i++) ldsm_x4(a[i], aaddr[i] + ks * 32);
            #pragma unroll
            for (int j = 0; j < 4; j++) ldsm_x2(b[j], baddr[j] + ks * 32);
            #pragma unroll
            for (int i = 0; i < 3; i++)
                #pragma unroll
                for (int j = 0; j < 4; j++) mma8(y[i][j], a[i], b[j]);
        }

        // epilogue: y + bo -> global
        #pragma unroll
        for (int i = 0; i < 3; i++) {
            int row = fmg * 48 + i * 16 + gid;
            #pragma unroll
            for (int j = 0; j < 4; j++) {
                int col = fng * 32 + j * 8 + 2 * tig;
                float b0 = bos[col], b1 = bos[col + 1];
                size_t base = ((size_t)cta * MR + row) * DM + col;
                *(float2*)(out + base)          = make_float2(y[i][j][0] + b0, y[i][j][1] + b1);
                *(float2*)(out + base + 8 * DM) = make_float2(y[i][j][2] + b0, y[i][j][3] + b1);
            }
        }
    }
}

extern "C" void kernel_launch(void* const* d_in, const int* in_sizes, int n_in,
                              void* d_out, int out_size) {
    const float* x   = (const float*)d_in[0];
    const float* vis = (const float*)d_in[1];
    const float* Wq  = (const float*)d_in[2];
    const float* bq  = (const float*)d_in[3];
    const float* Wk  = (const float*)d_in[4];
    const float* bk  = (const float*)d_in[5];
    const float* Wv  = (const float*)d_in[6];
    const float* bv  = (const float*)d_in[7];
    const float* Wo  = (const float*)d_in[8];
    const float* bo  = (const float*)d_in[9];
    const float* bsc = (const float*)d_in[10];
    const float* adj = (const float*)d_in[11];
    float* out = (float*)d_out;

    const int B = in_sizes[0] / (NJ * DM);      // 16384
    const int grid = B / TB;                    // 2048
    const size_t smem = SM_FLOATS * sizeof(float);  // 193472 B

    static bool attr_set = false;
    if (!attr_set) {
        cudaFuncSetAttribute(cross_joint_attn_kernel,
                             cudaFuncAttributeMaxDynamicSharedMemorySize, (int)smem);
        attr_set = true;
    }
    cross_joint_attn_kernel<<<grid, THREADS, smem>>>(
        x, vis, Wq, bq, Wk, bk, Wv, bv, Wo, bo, bsc, adj, out);
}